// round 1
// baseline (speedup 1.0000x reference)
#include <cuda_runtime.h>
#include <math.h>

#define NN   50000
#define EE   800000
#define EP   850000   // EE + NN self loops
#define IND  64
#define EDD  16
#define HH   8
#define DD   32
#define CC   256      // H*D
#define NMOL 500

// ---------------- scratch (static device globals; no allocation) ----------------
__device__ float g_ea_loop[NN * EDD];
__device__ int   g_counts[NN];
__device__ int   g_rowstart[NN + 1];
__device__ int   g_cursor[NN];
__device__ int   g_perm[EP];
__device__ int   g_srcs[EP];
__device__ int   g_dsts[EP];
__device__ float g_alpha[(size_t)EP * HH];
__device__ float g_asrc[NN * HH];
__device__ float g_adst[NN * HH];
__device__ float g_xl[(size_t)NN * CC];
__device__ float g_h0[(size_t)NN * CC];
__device__ float g_h1[(size_t)NN * CC];
__device__ float g_h2[(size_t)NN * CC];
__device__ float g_wea[EDD * HH];
__device__ float g_hpool[NMOL * CC];
__device__ float g_hcat[(size_t)NN * 1024];
__device__ float g_mlp1[(size_t)NN * 96];
__device__ float g_mlp2[(size_t)NN * 64];

// ---------------- init: zero ea_loop, counts=1 (self loop), zero hpool ----------------
__global__ void k_init() {
    int i = blockIdx.x * blockDim.x + threadIdx.x;
    if (i < NN * EDD) g_ea_loop[i] = 0.f;
    if (i < NN)       g_counts[i]  = 1;
    if (i < NMOL * CC) g_hpool[i]  = 0.f;
}

// ---------------- per-edge: accumulate ea_loop (fill='add') and in-degree ----------------
__global__ void k_eagg(const int* __restrict__ ei, const float* __restrict__ ea) {
    int idx = blockIdx.x * blockDim.x + threadIdx.x;
    if (idx >= EE * EDD) return;
    int e = idx >> 4, i = idx & 15;
    int d = ei[EE + e];
    atomicAdd(&g_ea_loop[d * EDD + i], ea[idx]);
    if (i == 0) atomicAdd(&g_counts[d], 1);
}

// ---------------- single-block exclusive scan over counts -> rowstart, cursor ----------------
__global__ void k_scan() {
    __shared__ int part[1024];
    int t = threadIdx.x;
    const int chunk = (NN + 1023) / 1024;
    int start = t * chunk;
    int end = start + chunk; if (end > NN) end = NN;
    int s = 0;
    for (int i = start; i < end; i++) s += g_counts[i];
    part[t] = s;
    __syncthreads();
    for (int off = 1; off < 1024; off <<= 1) {
        int u = (t >= off) ? part[t - off] : 0;
        __syncthreads();
        part[t] += u;
        __syncthreads();
    }
    int run = part[t] - s;  // exclusive prefix
    for (int i = start; i < end; i++) {
        g_rowstart[i] = run;
        g_cursor[i]   = run;
        run += g_counts[i];
    }
    if (t == 1023) g_rowstart[NN] = part[1023];
}

// ---------------- scatter edges (incl. self loops) into CSR order ----------------
__global__ void k_scatter(const int* __restrict__ ei) {
    int idx = blockIdx.x * blockDim.x + threadIdx.x;
    if (idx >= EP) return;
    int s, d;
    if (idx < EE) { s = ei[idx]; d = ei[EE + idx]; }
    else          { s = idx - EE; d = s; }
    int pos = atomicAdd(&g_cursor[d], 1);
    g_perm[pos] = idx;
    g_srcs[pos] = s;
    g_dsts[pos] = d;
}

// ---------------- Wea[i][h] = sum_d We[i, h*D+d] * ae[h,d] ----------------
__global__ void k_wea(const float* __restrict__ We, const float* __restrict__ ae) {
    int t = threadIdx.x;  // 128
    int i = t >> 3, h = t & 7;
    float s = 0.f;
    for (int dd = 0; dd < DD; dd++) s += We[i * CC + h * DD + dd] * ae[h * DD + dd];
    g_wea[i * HH + h] = s;
}

// ---------------- generic tiled SGEMM: C[M,Ncols] = A[M,K] @ B[K,Ncols] (+bias, act) ----------------
// BM=64, BN=64, BK=16, 256 threads, 4x4 microtile. K must be a multiple of 16.
__global__ void k_gemm(const float* __restrict__ A, const float* __restrict__ B,
                       float* __restrict__ C, const float* __restrict__ bias,
                       int M, int K, int Ncols, int act) {
    __shared__ float As[16][68];
    __shared__ float Bs[16][68];
    int m0 = blockIdx.x * 64;
    int n0 = blockIdx.y * 64;
    int t = threadIdx.x;
    int tr = t >> 4, tc = t & 15;

    int la_m = t >> 2;            // 0..63
    int la_k = (t & 3) * 4;       // 0,4,8,12
    int lb_k = t >> 4;            // 0..15
    int lb_n = (t & 15) * 4;      // 0..60

    float acc[4][4];
#pragma unroll
    for (int i = 0; i < 4; i++)
#pragma unroll
        for (int j = 0; j < 4; j++) acc[i][j] = 0.f;

    for (int k0 = 0; k0 < K; k0 += 16) {
        // load A tile (64 x 16), transposed into As[k][m]
        int gm = m0 + la_m;
        if (gm < M) {
            const float4 v = *reinterpret_cast<const float4*>(A + (size_t)gm * K + k0 + la_k);
            As[la_k + 0][la_m] = v.x;
            As[la_k + 1][la_m] = v.y;
            As[la_k + 2][la_m] = v.z;
            As[la_k + 3][la_m] = v.w;
        } else {
            As[la_k + 0][la_m] = 0.f;
            As[la_k + 1][la_m] = 0.f;
            As[la_k + 2][la_m] = 0.f;
            As[la_k + 3][la_m] = 0.f;
        }
        // load B tile (16 x 64) with column guard
        {
            int gk = k0 + lb_k;
            const float* bp = B + (size_t)gk * Ncols + n0 + lb_n;
            if (n0 + lb_n + 3 < Ncols) {
                const float4 v = *reinterpret_cast<const float4*>(bp);
                *reinterpret_cast<float4*>(&Bs[lb_k][lb_n]) = v;
            } else {
#pragma unroll
                for (int j = 0; j < 4; j++)
                    Bs[lb_k][lb_n + j] = (n0 + lb_n + j < Ncols) ? bp[j] : 0.f;
            }
        }
        __syncthreads();
#pragma unroll
        for (int kk = 0; kk < 16; kk++) {
            const float4 av = *reinterpret_cast<const float4*>(&As[kk][tr * 4]);
            const float4 bv = *reinterpret_cast<const float4*>(&Bs[kk][tc * 4]);
            float aa[4] = {av.x, av.y, av.z, av.w};
            float bb[4] = {bv.x, bv.y, bv.z, bv.w};
#pragma unroll
            for (int i = 0; i < 4; i++)
#pragma unroll
                for (int j = 0; j < 4; j++) acc[i][j] += aa[i] * bb[j];
        }
        __syncthreads();
    }

#pragma unroll
    for (int i = 0; i < 4; i++) {
        int gm = m0 + tr * 4 + i;
        if (gm >= M) continue;
#pragma unroll
        for (int j = 0; j < 4; j++) {
            int gn = n0 + tc * 4 + j;
            if (gn >= Ncols) continue;
            float v = acc[i][j];
            if (bias) v += bias[gn];
            if (act == 1) v = (v > 0.f) ? v : 0.01f * v;
            C[(size_t)gm * Ncols + gn] = v;
        }
    }
}

// ---------------- per-(node,head) attention scalars from xl ----------------
__global__ void k_attn(const float* __restrict__ as_, const float* __restrict__ ad_) {
    int idx = blockIdx.x * blockDim.x + threadIdx.x;
    if (idx >= NN * HH) return;
    int n = idx >> 3, h = idx & 7;
    const float* xr = &g_xl[(size_t)n * CC + h * DD];
    float ss = 0.f, sd = 0.f;
#pragma unroll
    for (int dd = 0; dd < DD; dd++) {
        float v = xr[dd];
        ss += v * as_[h * DD + dd];
        sd += v * ad_[h * DD + dd];
    }
    g_asrc[idx] = ss;
    g_adst[idx] = sd;
}

// ---------------- per-edge alpha (leaky-relu'd logits), in CSR order ----------------
__global__ void k_alpha(const float* __restrict__ edge_attr) {
    __shared__ float swea[EDD * HH];
    int t = threadIdx.x;
    if (t < EDD * HH) swea[t] = g_wea[t];
    __syncthreads();
    int pos = blockIdx.x * blockDim.x + t;
    if (pos >= EP) return;
    int e = g_perm[pos];
    const float* ear = (e < EE) ? (edge_attr + (size_t)e * EDD)
                                : (g_ea_loop + (size_t)(e - EE) * EDD);
    float eav[EDD];
#pragma unroll
    for (int i = 0; i < EDD; i++) eav[i] = ear[i];
    int s = g_srcs[pos], d = g_dsts[pos];
    float out[HH];
#pragma unroll
    for (int h = 0; h < HH; h++) out[h] = g_asrc[s * HH + h] + g_adst[d * HH + h];
#pragma unroll
    for (int i = 0; i < EDD; i++) {
        float ev = eav[i];
#pragma unroll
        for (int h = 0; h < HH; h++) out[h] += ev * swea[i * HH + h];
    }
#pragma unroll
    for (int h = 0; h < HH; h++) {
        float v = out[h];
        g_alpha[(size_t)pos * HH + h] = (v > 0.f) ? v : 0.2f * v;  // GAT slope 0.2
    }
}

// ---------------- per-node softmax + aggregate: block per node, 256 threads ----------------
__global__ void k_agg(float* __restrict__ out, const float* __restrict__ bias) {
    int n = blockIdx.x;
    int rs = g_rowstart[n], re = g_rowstart[n + 1];
    __shared__ float sm[HH], ssum[HH];
    int t = threadIdx.x;
    if (t < 64) {
        int h = t >> 3, j = t & 7;
        float m = -1e30f;
        for (int p = rs + j; p < re; p += 8) m = fmaxf(m, g_alpha[(size_t)p * HH + h]);
#pragma unroll
        for (int o = 1; o < 8; o <<= 1) m = fmaxf(m, __shfl_xor_sync(0xffffffffu, m, o, 8));
        float s = 0.f;
        for (int p = rs + j; p < re; p += 8) s += __expf(g_alpha[(size_t)p * HH + h] - m);
#pragma unroll
        for (int o = 1; o < 8; o <<= 1) s += __shfl_xor_sync(0xffffffffu, s, o, 8);
        if (j == 0) { sm[h] = m; ssum[h] = s; }
    }
    __syncthreads();
    int h = t >> 5;
    float m = sm[h];
    float inv = 1.0f / ssum[h];
    float acc = 0.f;
    for (int p = rs; p < re; p++) {
        float a = __expf(g_alpha[(size_t)p * HH + h] - m);
        int s = g_srcs[p];
        acc += a * g_xl[(size_t)s * CC + t];
    }
    out[(size_t)n * CC + t] = acc * inv + bias[t];
}

// ---------------- graph pooling (segment sum over batch) ----------------
__global__ void k_pool(const int* __restrict__ batch) {
    int idx = blockIdx.x * blockDim.x + threadIdx.x;
    if (idx >= NN * CC) return;
    int n = idx >> 8, c = idx & 255;
    atomicAdd(&g_hpool[batch[n] * CC + c], g_h2[idx]);
}

// ---------------- build concat [h1 | h2 | h3 | hpool[batch]] ----------------
__global__ void k_concat(const int* __restrict__ batch) {
    int idx = blockIdx.x * blockDim.x + threadIdx.x;
    if (idx >= NN * 1024) return;
    int n = idx >> 10, k = idx & 1023;
    float v;
    if      (k < 256) v = g_h0[(size_t)n * CC + k];
    else if (k < 512) v = g_h1[(size_t)n * CC + k - 256];
    else if (k < 768) v = g_h2[(size_t)n * CC + k - 512];
    else              v = g_hpool[batch[n] * CC + (k - 768)];
    g_hcat[(size_t)idx] = v;
}

// ---------------- final 64->1 + sigmoid ----------------
__global__ void k_mlp3(float* __restrict__ out, const float* __restrict__ lw3,
                       const float* __restrict__ lb3) {
    __shared__ float w[64];
    int t = threadIdx.x;
    if (t < 64) w[t] = lw3[t];
    __syncthreads();
    int n = blockIdx.x * blockDim.x + t;
    if (n >= NN) return;
    float s = lb3[0];
    const float* r = &g_mlp2[(size_t)n * 64];
#pragma unroll
    for (int k = 0; k < 64; k++) s += r[k] * w[k];
    out[n] = 1.0f / (1.0f + __expf(-s));
}

// ---------------- host launch ----------------
static float* symaddr(const void* sym) {
    void* p = nullptr;
    cudaGetSymbolAddress(&p, sym);
    return (float*)p;
}

extern "C" void kernel_launch(void* const* d_in, const int* in_sizes, int n_in,
                              void* d_out, int out_size) {
    const float* x     = (const float*)d_in[0];
    const int*   ei    = (const int*)d_in[1];
    const float* ea    = (const float*)d_in[2];
    const int*   batch = (const int*)d_in[3];
    const float *W[3], *as_[3], *ad_[3], *We[3], *ae[3], *b[3];
    for (int l = 0; l < 3; l++) {
        W[l]   = (const float*)d_in[4 + 6 * l];
        as_[l] = (const float*)d_in[5 + 6 * l];
        ad_[l] = (const float*)d_in[6 + 6 * l];
        We[l]  = (const float*)d_in[7 + 6 * l];
        ae[l]  = (const float*)d_in[8 + 6 * l];
        b[l]   = (const float*)d_in[9 + 6 * l];
    }
    const float* lw1 = (const float*)d_in[22];
    const float* lb1 = (const float*)d_in[23];
    const float* lw2 = (const float*)d_in[24];
    const float* lb2 = (const float*)d_in[25];
    const float* lw3 = (const float*)d_in[26];
    const float* lb3 = (const float*)d_in[27];
    float* out = (float*)d_out;

    float* p_xl   = symaddr(g_xl);
    float* p_h[3] = {symaddr(g_h0), symaddr(g_h1), symaddr(g_h2)};
    float* p_hcat = symaddr(g_hcat);
    float* p_m1   = symaddr(g_mlp1);
    float* p_m2   = symaddr(g_mlp2);

    // graph preprocessing (CSR by dst + self-loop edge_attr)
    k_init<<<(NN * EDD + 255) / 256, 256>>>();
    k_eagg<<<(EE * EDD + 255) / 256, 256>>>(ei, ea);
    k_scan<<<1, 1024>>>();
    k_scatter<<<(EP + 255) / 256, 256>>>(ei);

    const float* lin[3] = {x, p_h[0], p_h[1]};
    const int kdim[3]   = {IND, CC, CC};
    const int gx = (NN + 63) / 64;

    for (int l = 0; l < 3; l++) {
        k_gemm<<<dim3(gx, CC / 64), 256>>>(lin[l], W[l], p_xl, nullptr, NN, kdim[l], CC, 0);
        k_attn<<<(NN * HH + 255) / 256, 256>>>(as_[l], ad_[l]);
        k_wea<<<1, 128>>>(We[l], ae[l]);
        k_alpha<<<(EP + 255) / 256, 256>>>(ea);
        k_agg<<<NN, 256>>>(p_h[l], b[l]);
    }

    k_pool<<<(NN * CC + 255) / 256, 256>>>(batch);
    k_concat<<<(NN * 1024 + 255) / 256, 256>>>(batch);
    k_gemm<<<dim3(gx, 2), 256>>>(p_hcat, lw1, p_m1, lb1, NN, 1024, 96, 1);
    k_gemm<<<dim3(gx, 1), 256>>>(p_m1, lw2, p_m2, lb2, NN, 96, 64, 1);
    k_mlp3<<<(NN + 255) / 256, 256>>>(out, lw3, lb3);
}

// round 2
// speedup vs baseline: 1.0823x; 1.0823x over previous
#include <cuda_runtime.h>
#include <math.h>

#define NN   50000
#define EE   800000
#define EP   850000   // EE + NN self loops
#define IND  64
#define EDD  16
#define HH   8
#define DD   32
#define CC   256      // H*D
#define NMOL 500

// ---------------- scratch (static device globals; no allocation) ----------------
__device__ float g_ea_loop[NN * EDD];
__device__ int   g_counts[NN];
__device__ int   g_rowstart[NN + 1];
__device__ int   g_cursor[NN];
__device__ int   g_perm[EP];
__device__ int   g_srcs[EP];
__device__ float g_alpha[(size_t)EP * HH];
__device__ float g_asrc[NN * HH];
__device__ float g_adst[NN * HH];
__device__ float g_xl[(size_t)NN * CC];
__device__ float g_h0[(size_t)NN * CC];
__device__ float g_h1[(size_t)NN * CC];
__device__ float g_h2[(size_t)NN * CC];
__device__ float g_wea[3 * EDD * HH];
__device__ float g_hpool[NMOL * CC];
__device__ float g_mlp1[(size_t)NN * 96];
__device__ float g_mlp2[(size_t)NN * 64];

// ---------------- init: counts=1 (self loop), zero hpool ----------------
__global__ void k_init() {
    int i = blockIdx.x * blockDim.x + threadIdx.x;
    if (i < NN)        g_counts[i] = 1;
    if (i < NMOL * CC) g_hpool[i]  = 0.f;
}

// ---------------- in-degree count: one atomic per edge ----------------
__global__ void k_count(const int* __restrict__ ei) {
    int e = blockIdx.x * blockDim.x + threadIdx.x;
    if (e < EE) atomicAdd(&g_counts[ei[EE + e]], 1);
}

// ---------------- single-block exclusive scan over counts -> rowstart, cursor ----------------
__global__ void k_scan() {
    __shared__ int part[1024];
    int t = threadIdx.x;
    const int chunk = (NN + 1023) / 1024;
    int start = t * chunk;
    int end = start + chunk; if (end > NN) end = NN;
    int s = 0;
    for (int i = start; i < end; i++) s += g_counts[i];
    part[t] = s;
    __syncthreads();
    for (int off = 1; off < 1024; off <<= 1) {
        int u = (t >= off) ? part[t - off] : 0;
        __syncthreads();
        part[t] += u;
        __syncthreads();
    }
    int run = part[t] - s;  // exclusive prefix
    for (int i = start; i < end; i++) {
        g_rowstart[i] = run;
        g_cursor[i]   = run;
        run += g_counts[i];
    }
    if (t == 1023) g_rowstart[NN] = part[1023];
}

// ---------------- scatter edges (incl. self loops) into CSR order ----------------
__global__ void k_scatter(const int* __restrict__ ei) {
    int idx = blockIdx.x * blockDim.x + threadIdx.x;
    if (idx >= EP) return;
    int s, d;
    if (idx < EE) { s = ei[idx]; d = ei[EE + idx]; }
    else          { s = idx - EE; d = s; }
    int pos = atomicAdd(&g_cursor[d], 1);
    g_perm[pos] = idx;
    g_srcs[pos] = s;
}

// ---------------- self-loop edge_attr (fill='add'): sum over CSR row's real edges ----------------
__global__ void k_ealoop(const float* __restrict__ ea) {
    int idx = blockIdx.x * blockDim.x + threadIdx.x;
    if (idx >= NN * EDD) return;
    int n = idx >> 4, i = idx & 15;
    int rs = g_rowstart[n], re = g_rowstart[n + 1];
    float s = 0.f;
    for (int p = rs; p < re; p++) {
        int e = g_perm[p];
        if (e < EE) s += ea[(size_t)e * EDD + i];
    }
    g_ea_loop[idx] = s;
}

// ---------------- Wea[l][i][h] = sum_d We_l[i, h*D+d] * ae_l[h,d], all 3 layers ----------------
__global__ void k_wea3(const float* __restrict__ We0, const float* __restrict__ ae0,
                       const float* __restrict__ We1, const float* __restrict__ ae1,
                       const float* __restrict__ We2, const float* __restrict__ ae2) {
    int t = threadIdx.x;  // 384
    int l = t >> 7, r = t & 127;
    int i = r >> 3, h = r & 7;
    const float* We = (l == 0) ? We0 : (l == 1) ? We1 : We2;
    const float* ae = (l == 0) ? ae0 : (l == 1) ? ae1 : ae2;
    float s = 0.f;
    for (int dd = 0; dd < DD; dd++) s += We[i * CC + h * DD + dd] * ae[h * DD + dd];
    g_wea[l * EDD * HH + i * HH + h] = s;
}

// ---------------- tiled SGEMM: C[M,N] = A[M,K] @ B[K,N] (+bias, leaky act) ----------------
// BM=128, BN=64, BK=16, 256 threads, 8x4 microtile. K must be a multiple of 16.
// MODE 0: A is a plain row-major matrix.
// MODE 1: A row m is the virtual concat [h0[m] | h1[m] | h2[m] | hpool[batch[m]]], K=1024.
template<int MODE>
__global__ void k_gemm(const float* __restrict__ A, const float* __restrict__ B,
                       float* __restrict__ C, const float* __restrict__ bias,
                       int M, int K, int N, int act, const int* __restrict__ batch) {
    __shared__ float As[16][128];
    __shared__ float Bs[16][68];
    int m0 = blockIdx.x * 128;
    int n0 = blockIdx.y * 64;
    int t  = threadIdx.x;
    int la_m = t >> 1;
    int la_k = (t & 1) * 8;
    int lb_k = t >> 4;
    int lb_n = (t & 15) * 4;
    int tr = t >> 4, tc = t & 15;

    float acc[8][4];
#pragma unroll
    for (int i = 0; i < 8; i++)
#pragma unroll
        for (int j = 0; j < 4; j++) acc[i][j] = 0.f;

    int gm_l = m0 + la_m;
    int bidx = 0;
    if (MODE == 1 && gm_l < M) bidx = batch[gm_l];

    for (int k0 = 0; k0 < K; k0 += 16) {
        // ---- load A tile (128 x 16) transposed into As[k][m] ----
#pragma unroll
        for (int half = 0; half < 2; half++) {
            int kk = la_k + half * 4;
            float4 v = make_float4(0.f, 0.f, 0.f, 0.f);
            if (gm_l < M) {
                int gk = k0 + kk;
                if (MODE == 0) {
                    v = *reinterpret_cast<const float4*>(A + (size_t)gm_l * K + gk);
                } else {
                    const float* src;
                    if      (gk < 256) src = g_h0 + (size_t)gm_l * CC + gk;
                    else if (gk < 512) src = g_h1 + (size_t)gm_l * CC + (gk - 256);
                    else if (gk < 768) src = g_h2 + (size_t)gm_l * CC + (gk - 512);
                    else               src = g_hpool + (size_t)bidx * CC + (gk - 768);
                    v = *reinterpret_cast<const float4*>(src);
                }
            }
            As[kk + 0][la_m] = v.x;
            As[kk + 1][la_m] = v.y;
            As[kk + 2][la_m] = v.z;
            As[kk + 3][la_m] = v.w;
        }
        // ---- load B tile (16 x 64) with column guard ----
        {
            int gk = k0 + lb_k;
            int gn = n0 + lb_n;
            const float* bp = B + (size_t)gk * N + gn;
            if (gn + 3 < N) {
                *reinterpret_cast<float4*>(&Bs[lb_k][lb_n]) =
                    *reinterpret_cast<const float4*>(bp);
            } else {
#pragma unroll
                for (int j = 0; j < 4; j++)
                    Bs[lb_k][lb_n + j] = (gn + j < N) ? bp[j] : 0.f;
            }
        }
        __syncthreads();
#pragma unroll
        for (int kk = 0; kk < 16; kk++) {
            float4 a0 = *reinterpret_cast<const float4*>(&As[kk][tr * 8]);
            float4 a1 = *reinterpret_cast<const float4*>(&As[kk][tr * 8 + 4]);
            float4 bv = *reinterpret_cast<const float4*>(&Bs[kk][tc * 4]);
            float aa[8] = {a0.x, a0.y, a0.z, a0.w, a1.x, a1.y, a1.z, a1.w};
            float bb[4] = {bv.x, bv.y, bv.z, bv.w};
#pragma unroll
            for (int i = 0; i < 8; i++)
#pragma unroll
                for (int j = 0; j < 4; j++) acc[i][j] += aa[i] * bb[j];
        }
        __syncthreads();
    }

#pragma unroll
    for (int i = 0; i < 8; i++) {
        int gm = m0 + tr * 8 + i;
        if (gm >= M) continue;
#pragma unroll
        for (int j = 0; j < 4; j++) {
            int gn = n0 + tc * 4 + j;
            if (gn >= N) continue;
            float v = acc[i][j];
            if (bias) v += bias[gn];
            if (act == 1) v = (v > 0.f) ? v : 0.01f * v;
            C[(size_t)gm * N + gn] = v;
        }
    }
}

// ---------------- per-(node,head) attention scalars from xl ----------------
__global__ void k_attn(const float* __restrict__ as_, const float* __restrict__ ad_) {
    int idx = blockIdx.x * blockDim.x + threadIdx.x;
    if (idx >= NN * HH) return;
    int n = idx >> 3, h = idx & 7;
    const float* xr = &g_xl[(size_t)n * CC + h * DD];
    float ss = 0.f, sd = 0.f;
#pragma unroll
    for (int dd = 0; dd < DD; dd++) {
        float v = xr[dd];
        ss += v * as_[h * DD + dd];
        sd += v * ad_[h * DD + dd];
    }
    g_asrc[idx] = ss;
    g_adst[idx] = sd;
}

// ---------------- per-edge alpha (leaky-relu'd logits), in CSR order ----------------
__global__ void k_alpha(const float* __restrict__ edge_attr, int layer,
                        const int* __restrict__ ei) {
    __shared__ float swea[EDD * HH];
    int t = threadIdx.x;
    if (t < EDD * HH) swea[t] = g_wea[layer * EDD * HH + t];
    __syncthreads();
    int pos = blockIdx.x * blockDim.x + t;
    if (pos >= EP) return;
    int e = g_perm[pos];
    int s = g_srcs[pos];
    int d;
    const float* ear;
    if (e < EE) { d = ei[EE + e]; ear = edge_attr + (size_t)e * EDD; }
    else        { d = e - EE;     ear = g_ea_loop + (size_t)(e - EE) * EDD; }
    float eav[EDD];
#pragma unroll
    for (int i = 0; i < EDD; i++) eav[i] = ear[i];
    float out[HH];
#pragma unroll
    for (int h = 0; h < HH; h++) out[h] = g_asrc[s * HH + h] + g_adst[d * HH + h];
#pragma unroll
    for (int i = 0; i < EDD; i++) {
        float ev = eav[i];
#pragma unroll
        for (int h = 0; h < HH; h++) out[h] += ev * swea[i * HH + h];
    }
#pragma unroll
    for (int h = 0; h < HH; h++) {
        float v = out[h];
        g_alpha[(size_t)pos * HH + h] = (v > 0.f) ? v : 0.2f * v;  // GAT slope 0.2
    }
}

// ---------------- per-node softmax + aggregate: block per node, 256 threads ----------------
__global__ void k_agg(float* __restrict__ out, const float* __restrict__ bias) {
    int n = blockIdx.x;
    int rs = g_rowstart[n], re = g_rowstart[n + 1];
    __shared__ float sm[HH], ssum[HH];
    int t = threadIdx.x;
    if (t < 64) {
        int h = t >> 3, j = t & 7;
        float m = -1e30f;
        for (int p = rs + j; p < re; p += 8) m = fmaxf(m, g_alpha[(size_t)p * HH + h]);
#pragma unroll
        for (int o = 1; o < 8; o <<= 1) m = fmaxf(m, __shfl_xor_sync(0xffffffffu, m, o, 8));
        float s = 0.f;
        for (int p = rs + j; p < re; p += 8) s += __expf(g_alpha[(size_t)p * HH + h] - m);
#pragma unroll
        for (int o = 1; o < 8; o <<= 1) s += __shfl_xor_sync(0xffffffffu, s, o, 8);
        if (j == 0) { sm[h] = m; ssum[h] = s; }
    }
    __syncthreads();
    int h = t >> 5;
    float m = sm[h];
    float inv = 1.0f / ssum[h];
    float acc = 0.f;
    for (int p = rs; p < re; p++) {
        float a = __expf(g_alpha[(size_t)p * HH + h] - m);
        int s = g_srcs[p];
        acc += a * g_xl[(size_t)s * CC + t];
    }
    out[(size_t)n * CC + t] = acc * inv + bias[t];
}

// ---------------- graph pooling (segment sum over batch) ----------------
__global__ void k_pool(const int* __restrict__ batch) {
    int idx = blockIdx.x * blockDim.x + threadIdx.x;
    if (idx >= NN * CC) return;
    int n = idx >> 8, c = idx & 255;
    atomicAdd(&g_hpool[batch[n] * CC + c], g_h2[idx]);
}

// ---------------- final 64->1 + sigmoid ----------------
__global__ void k_mlp3(float* __restrict__ out, const float* __restrict__ lw3,
                       const float* __restrict__ lb3) {
    __shared__ float w[64];
    int t = threadIdx.x;
    if (t < 64) w[t] = lw3[t];
    __syncthreads();
    int n = blockIdx.x * blockDim.x + t;
    if (n >= NN) return;
    float s = lb3[0];
    const float* r = &g_mlp2[(size_t)n * 64];
#pragma unroll
    for (int k = 0; k < 64; k++) s += r[k] * w[k];
    out[n] = 1.0f / (1.0f + __expf(-s));
}

// ---------------- host launch ----------------
static float* symaddr(const void* sym) {
    void* p = nullptr;
    cudaGetSymbolAddress(&p, sym);
    return (float*)p;
}

extern "C" void kernel_launch(void* const* d_in, const int* in_sizes, int n_in,
                              void* d_out, int out_size) {
    const float* x     = (const float*)d_in[0];
    const int*   ei    = (const int*)d_in[1];
    const float* ea    = (const float*)d_in[2];
    const int*   batch = (const int*)d_in[3];
    const float *W[3], *as_[3], *ad_[3], *We[3], *ae[3], *b[3];
    for (int l = 0; l < 3; l++) {
        W[l]   = (const float*)d_in[4 + 6 * l];
        as_[l] = (const float*)d_in[5 + 6 * l];
        ad_[l] = (const float*)d_in[6 + 6 * l];
        We[l]  = (const float*)d_in[7 + 6 * l];
        ae[l]  = (const float*)d_in[8 + 6 * l];
        b[l]   = (const float*)d_in[9 + 6 * l];
    }
    const float* lw1 = (const float*)d_in[22];
    const float* lb1 = (const float*)d_in[23];
    const float* lw2 = (const float*)d_in[24];
    const float* lb2 = (const float*)d_in[25];
    const float* lw3 = (const float*)d_in[26];
    const float* lb3 = (const float*)d_in[27];
    float* out = (float*)d_out;

    float* p_xl   = symaddr(g_xl);
    float* p_h[3] = {symaddr(g_h0), symaddr(g_h1), symaddr(g_h2)};
    float* p_m1   = symaddr(g_mlp1);
    float* p_m2   = symaddr(g_mlp2);

    // graph preprocessing (CSR by dst + self-loop edge_attr)
    k_init<<<(NMOL * CC + 255) / 256, 256>>>();
    k_count<<<(EE + 255) / 256, 256>>>(ei);
    k_scan<<<1, 1024>>>();
    k_scatter<<<(EP + 255) / 256, 256>>>(ei);
    k_ealoop<<<(NN * EDD + 255) / 256, 256>>>(ea);
    k_wea3<<<1, 384>>>(We[0], ae[0], We[1], ae[1], We[2], ae[2]);

    const float* lin[3] = {x, p_h[0], p_h[1]};
    const int kdim[3]   = {IND, CC, CC};
    const int gx = (NN + 127) / 128;

    for (int l = 0; l < 3; l++) {
        k_gemm<0><<<dim3(gx, CC / 64), 256>>>(lin[l], W[l], p_xl, nullptr,
                                              NN, kdim[l], CC, 0, nullptr);
        k_attn<<<(NN * HH + 255) / 256, 256>>>(as_[l], ad_[l]);
        k_alpha<<<(EP + 255) / 256, 256>>>(ea, l, ei);
        k_agg<<<NN, 256>>>(p_h[l], b[l]);
    }

    k_pool<<<(NN * CC + 255) / 256, 256>>>(batch);
    // MLP1 with fused concat gather: K = 1024, N = 96
    k_gemm<1><<<dim3(gx, 2), 256>>>(nullptr, lw1, p_m1, lb1, NN, 1024, 96, 1, batch);
    k_gemm<0><<<dim3(gx, 1), 256>>>(p_m1, lw2, p_m2, lb2, NN, 96, 64, 1, nullptr);
    k_mlp3<<<(NN + 255) / 256, 256>>>(out, lw3, lb3);
}

// round 3
// speedup vs baseline: 1.1000x; 1.0164x over previous
#include <cuda_runtime.h>
#include <math.h>
#include <stdint.h>

#define NN   50000
#define EE   800000
#define EP   850000   // EE + NN self loops
#define IND  64
#define EDD  16
#define HH   8
#define DD   32
#define CC   256      // H*D
#define NMOL 500

// ---------------- scratch (static device globals; no allocation) ----------------
__device__ float g_ea_loop[NN * EDD];
__device__ int   g_counts[NN];
__device__ int   g_rowstart[NN + 1];
__device__ int   g_cursor[NN];
__device__ int   g_perm[EP];
__device__ int   g_srcs[EP];
__device__ float g_alpha[(size_t)EP * HH];
__device__ float g_asrc[NN * HH];
__device__ float g_adst[NN * HH];
__device__ float g_xl[(size_t)NN * CC];
__device__ float g_h0[(size_t)NN * CC];
__device__ float g_h1[(size_t)NN * CC];
__device__ float g_h2[(size_t)NN * CC];
__device__ float g_wea[3 * EDD * HH];
__device__ float g_hpool[NMOL * CC];
__device__ float g_mlp1[(size_t)NN * 96];
__device__ float g_mlp2[(size_t)NN * 64];

// ---------------- init: counts=1 (self loop), zero hpool ----------------
__global__ void k_init() {
    int i = blockIdx.x * blockDim.x + threadIdx.x;
    if (i < NN)        g_counts[i] = 1;
    if (i < NMOL * CC) g_hpool[i]  = 0.f;
}

// ---------------- in-degree count: one atomic per edge ----------------
__global__ void k_count(const int* __restrict__ ei) {
    int e = blockIdx.x * blockDim.x + threadIdx.x;
    if (e < EE) atomicAdd(&g_counts[ei[EE + e]], 1);
}

// ---------------- single-block exclusive scan over counts -> rowstart, cursor ----------------
__global__ void k_scan() {
    __shared__ int part[1024];
    int t = threadIdx.x;
    const int chunk = (NN + 1023) / 1024;
    int start = t * chunk;
    int end = start + chunk; if (end > NN) end = NN;
    int s = 0;
    for (int i = start; i < end; i++) s += g_counts[i];
    part[t] = s;
    __syncthreads();
    for (int off = 1; off < 1024; off <<= 1) {
        int u = (t >= off) ? part[t - off] : 0;
        __syncthreads();
        part[t] += u;
        __syncthreads();
    }
    int run = part[t] - s;  // exclusive prefix
    for (int i = start; i < end; i++) {
        g_rowstart[i] = run;
        g_cursor[i]   = run;
        run += g_counts[i];
    }
    if (t == 1023) g_rowstart[NN] = part[1023];
}

// ---------------- scatter edges (incl. self loops) into CSR order ----------------
__global__ void k_scatter(const int* __restrict__ ei) {
    int idx = blockIdx.x * blockDim.x + threadIdx.x;
    if (idx >= EP) return;
    int s, d;
    if (idx < EE) { s = ei[idx]; d = ei[EE + idx]; }
    else          { s = idx - EE; d = s; }
    int pos = atomicAdd(&g_cursor[d], 1);
    g_perm[pos] = idx;
    g_srcs[pos] = s;
}

// ---------------- self-loop edge_attr (fill='add'): sum over CSR row's real edges ----------------
__global__ void k_ealoop(const float* __restrict__ ea) {
    int idx = blockIdx.x * blockDim.x + threadIdx.x;
    if (idx >= NN * EDD) return;
    int n = idx >> 4, i = idx & 15;
    int rs = g_rowstart[n], re = g_rowstart[n + 1];
    float s = 0.f;
    for (int p = rs; p < re; p++) {
        int e = g_perm[p];
        if (e < EE) s += ea[(size_t)e * EDD + i];
    }
    g_ea_loop[idx] = s;
}

// ---------------- Wea[l][i][h] = sum_d We_l[i, h*D+d] * ae_l[h,d], all 3 layers ----------------
__global__ void k_wea3(const float* __restrict__ We0, const float* __restrict__ ae0,
                       const float* __restrict__ We1, const float* __restrict__ ae1,
                       const float* __restrict__ We2, const float* __restrict__ ae2) {
    int t = threadIdx.x;  // 384
    int l = t >> 7, r = t & 127;
    int i = r >> 3, h = r & 7;
    const float* We = (l == 0) ? We0 : (l == 1) ? We1 : We2;
    const float* ae = (l == 0) ? ae0 : (l == 1) ? ae1 : ae2;
    float s = 0.f;
    for (int dd = 0; dd < DD; dd++) s += We[i * CC + h * DD + dd] * ae[h * DD + dd];
    g_wea[l * EDD * HH + i * HH + h] = s;
}

// ---------------- TF32 helpers ----------------
__device__ __forceinline__ uint32_t f2tf32(float x) {
    uint32_t r;
    asm("cvt.rna.tf32.f32 %0, %1;" : "=r"(r) : "f"(x));
    return r;
}
__device__ __forceinline__ void split_tf32(float x, uint32_t& hi, uint32_t& lo) {
    hi = f2tf32(x);
    lo = f2tf32(x - __uint_as_float(hi));
}
__device__ __forceinline__ void mma_tf32(float* d, const uint32_t* a, const uint32_t* b) {
    asm volatile(
        "mma.sync.aligned.m16n8k8.row.col.f32.tf32.tf32.f32 "
        "{%0,%1,%2,%3}, {%4,%5,%6,%7}, {%8,%9}, {%0,%1,%2,%3};\n"
        : "+f"(d[0]), "+f"(d[1]), "+f"(d[2]), "+f"(d[3])
        : "r"(a[0]), "r"(a[1]), "r"(a[2]), "r"(a[3]), "r"(b[0]), "r"(b[1]));
}

// ---------------- tensor-core GEMM (tf32x3): C[M,N] = A[M,K] @ B[K,N] (+bias, leaky) ----------------
// BM=128, BN=64, BK=16. 256 threads = 8 warps (4 along M x 2 along N), warp tile 32x32.
// MODE 0: A plain row-major. MODE 1: virtual concat row [h0|h1|h2|hpool[batch]], K=1024.
template<int MODE>
__global__ void k_gemm_tc(const float* __restrict__ A, const float* __restrict__ B,
                          float* __restrict__ C, const float* __restrict__ bias,
                          int M, int K, int N, int act, const int* __restrict__ batch) {
    __shared__ uint32_t As_hi[128][20];
    __shared__ uint32_t As_lo[128][20];
    __shared__ uint32_t Bs_hi[16][72];
    __shared__ uint32_t Bs_lo[16][72];

    const int t    = threadIdx.x;
    const int m0   = blockIdx.x * 128;
    const int n0   = blockIdx.y * 64;
    const int warp = t >> 5, lane = t & 31;
    const int wm = (warp & 3) * 32;     // warp row offset in tile
    const int wn = (warp >> 2) * 32;    // warp col offset in tile
    const int g  = lane >> 2, tg = lane & 3;

    // A tile loader: 2 rows per thread (row, row+64), 4 consecutive k each
    const int ar  = t >> 2;           // 0..63
    const int ac4 = (t & 3) * 4;      // 0,4,8,12
    // B tile loader: 1 float4 per thread
    const int br  = t >> 4;           // 0..15
    const int bc4 = (t & 15) * 4;     // 0..60

    int bidx0 = 0, bidx1 = 0;
    if (MODE == 1) {
        if (m0 + ar < M)      bidx0 = batch[m0 + ar];
        if (m0 + ar + 64 < M) bidx1 = batch[m0 + ar + 64];
    }

    float acc[2][4][4];
#pragma unroll
    for (int i = 0; i < 2; i++)
#pragma unroll
        for (int j = 0; j < 4; j++)
#pragma unroll
            for (int c = 0; c < 4; c++) acc[i][j][c] = 0.f;

    for (int k0 = 0; k0 < K; k0 += 16) {
        // ---- load A tile (128 x 16), split hi/lo ----
#pragma unroll
        for (int r = 0; r < 2; r++) {
            int row = ar + r * 64;
            int gm  = m0 + row;
            float4 v = make_float4(0.f, 0.f, 0.f, 0.f);
            if (gm < M) {
                int gk = k0 + ac4;
                if (MODE == 0) {
                    v = *reinterpret_cast<const float4*>(A + (size_t)gm * K + gk);
                } else {
                    int bidx = r ? bidx1 : bidx0;
                    const float* src;
                    if      (gk < 256) src = g_h0 + (size_t)gm * CC + gk;
                    else if (gk < 512) src = g_h1 + (size_t)gm * CC + (gk - 256);
                    else if (gk < 768) src = g_h2 + (size_t)gm * CC + (gk - 512);
                    else               src = g_hpool + (size_t)bidx * CC + (gk - 768);
                    v = *reinterpret_cast<const float4*>(src);
                }
            }
            float vv[4] = {v.x, v.y, v.z, v.w};
#pragma unroll
            for (int c = 0; c < 4; c++) {
                uint32_t hi, lo;
                split_tf32(vv[c], hi, lo);
                As_hi[row][ac4 + c] = hi;
                As_lo[row][ac4 + c] = lo;
            }
        }
        // ---- load B tile (16 x 64), split hi/lo ----
        {
            int gk = k0 + br;
            int gn = n0 + bc4;
            float vv[4] = {0.f, 0.f, 0.f, 0.f};
            const float* bp = B + (size_t)gk * N + gn;
            if (gn + 3 < N) {
                float4 v = *reinterpret_cast<const float4*>(bp);
                vv[0] = v.x; vv[1] = v.y; vv[2] = v.z; vv[3] = v.w;
            } else {
#pragma unroll
                for (int c = 0; c < 4; c++) if (gn + c < N) vv[c] = bp[c];
            }
#pragma unroll
            for (int c = 0; c < 4; c++) {
                uint32_t hi, lo;
                split_tf32(vv[c], hi, lo);
                Bs_hi[br][bc4 + c] = hi;
                Bs_lo[br][bc4 + c] = lo;
            }
        }
        __syncthreads();

#pragma unroll
        for (int ks = 0; ks < 2; ks++) {
            const int kk = ks * 8;
            uint32_t ah[2][4], al[2][4];
#pragma unroll
            for (int i2 = 0; i2 < 2; i2++) {
                int rb = wm + i2 * 16;
                ah[i2][0] = As_hi[rb + g     ][kk + tg];
                ah[i2][1] = As_hi[rb + g + 8 ][kk + tg];
                ah[i2][2] = As_hi[rb + g     ][kk + tg + 4];
                ah[i2][3] = As_hi[rb + g + 8 ][kk + tg + 4];
                al[i2][0] = As_lo[rb + g     ][kk + tg];
                al[i2][1] = As_lo[rb + g + 8 ][kk + tg];
                al[i2][2] = As_lo[rb + g     ][kk + tg + 4];
                al[i2][3] = As_lo[rb + g + 8 ][kk + tg + 4];
            }
            uint32_t bh[4][2], bl[4][2];
#pragma unroll
            for (int j = 0; j < 4; j++) {
                int cb = wn + j * 8 + g;
                bh[j][0] = Bs_hi[kk + tg    ][cb];
                bh[j][1] = Bs_hi[kk + tg + 4][cb];
                bl[j][0] = Bs_lo[kk + tg    ][cb];
                bl[j][1] = Bs_lo[kk + tg + 4][cb];
            }
#pragma unroll
            for (int i2 = 0; i2 < 2; i2++)
#pragma unroll
                for (int j = 0; j < 4; j++) {
                    mma_tf32(acc[i2][j], ah[i2], bl[j]);   // hi * lo
                    mma_tf32(acc[i2][j], al[i2], bh[j]);   // lo * hi
                    mma_tf32(acc[i2][j], ah[i2], bh[j]);   // hi * hi
                }
        }
        __syncthreads();
    }

    // ---- epilogue ----
#pragma unroll
    for (int i2 = 0; i2 < 2; i2++) {
#pragma unroll
        for (int j = 0; j < 4; j++) {
            int col = n0 + wn + j * 8 + tg * 2;
#pragma unroll
            for (int rr = 0; rr < 2; rr++) {
                int row = m0 + wm + i2 * 16 + g + rr * 8;
                if (row >= M || col >= N) continue;
                float v0 = acc[i2][j][rr * 2 + 0];
                float v1 = acc[i2][j][rr * 2 + 1];
                if (bias) { v0 += bias[col]; v1 += bias[col + 1]; }
                if (act == 1) {
                    v0 = (v0 > 0.f) ? v0 : 0.01f * v0;
                    v1 = (v1 > 0.f) ? v1 : 0.01f * v1;
                }
                *reinterpret_cast<float2*>(C + (size_t)row * N + col) = make_float2(v0, v1);
            }
        }
    }
}

// ---------------- per-(node,head) attention scalars from xl ----------------
__global__ void k_attn(const float* __restrict__ as_, const float* __restrict__ ad_) {
    int idx = blockIdx.x * blockDim.x + threadIdx.x;
    if (idx >= NN * HH) return;
    int n = idx >> 3, h = idx & 7;
    const float* xr = &g_xl[(size_t)n * CC + h * DD];
    float ss = 0.f, sd = 0.f;
#pragma unroll
    for (int dd = 0; dd < DD; dd++) {
        float v = xr[dd];
        ss += v * as_[h * DD + dd];
        sd += v * ad_[h * DD + dd];
    }
    g_asrc[idx] = ss;
    g_adst[idx] = sd;
}

// ---------------- per-edge alpha (leaky-relu'd logits), in CSR order ----------------
__global__ void k_alpha(const float* __restrict__ edge_attr, int layer,
                        const int* __restrict__ ei) {
    __shared__ float swea[EDD * HH];
    int t = threadIdx.x;
    if (t < EDD * HH) swea[t] = g_wea[layer * EDD * HH + t];
    __syncthreads();
    int pos = blockIdx.x * blockDim.x + t;
    if (pos >= EP) return;
    int e = g_perm[pos];
    int s = g_srcs[pos];
    int d;
    const float* ear;
    if (e < EE) { d = ei[EE + e]; ear = edge_attr + (size_t)e * EDD; }
    else        { d = e - EE;     ear = g_ea_loop + (size_t)(e - EE) * EDD; }
    float eav[EDD];
#pragma unroll
    for (int i = 0; i < EDD; i++) eav[i] = ear[i];
    float out[HH];
#pragma unroll
    for (int h = 0; h < HH; h++) out[h] = g_asrc[s * HH + h] + g_adst[d * HH + h];
#pragma unroll
    for (int i = 0; i < EDD; i++) {
        float ev = eav[i];
#pragma unroll
        for (int h = 0; h < HH; h++) out[h] += ev * swea[i * HH + h];
    }
#pragma unroll
    for (int h = 0; h < HH; h++) {
        float v = out[h];
        g_alpha[(size_t)pos * HH + h] = (v > 0.f) ? v : 0.2f * v;  // GAT slope 0.2
    }
}

// ---------------- per-node softmax + aggregate: block per node, 256 threads ----------------
__global__ void k_agg(float* __restrict__ out, const float* __restrict__ bias) {
    int n = blockIdx.x;
    int rs = g_rowstart[n], re = g_rowstart[n + 1];
    __shared__ float sm[HH], ssum[HH];
    int t = threadIdx.x;
    if (t < 64) {
        int h = t >> 3, j = t & 7;
        float m = -1e30f;
        for (int p = rs + j; p < re; p += 8) m = fmaxf(m, g_alpha[(size_t)p * HH + h]);
#pragma unroll
        for (int o = 1; o < 8; o <<= 1) m = fmaxf(m, __shfl_xor_sync(0xffffffffu, m, o, 8));
        float s = 0.f;
        for (int p = rs + j; p < re; p += 8) s += __expf(g_alpha[(size_t)p * HH + h] - m);
#pragma unroll
        for (int o = 1; o < 8; o <<= 1) s += __shfl_xor_sync(0xffffffffu, s, o, 8);
        if (j == 0) { sm[h] = m; ssum[h] = s; }
    }
    __syncthreads();
    int h = t >> 5;
    float m = sm[h];
    float inv = 1.0f / ssum[h];
    float acc = 0.f;
    for (int p = rs; p < re; p++) {
        float a = __expf(g_alpha[(size_t)p * HH + h] - m);
        int s = g_srcs[p];
        acc += a * g_xl[(size_t)s * CC + t];
    }
    out[(size_t)n * CC + t] = acc * inv + bias[t];
}

// ---------------- graph pooling (segment sum over batch) ----------------
__global__ void k_pool(const int* __restrict__ batch) {
    int idx = blockIdx.x * blockDim.x + threadIdx.x;
    if (idx >= NN * CC) return;
    int n = idx >> 8, c = idx & 255;
    atomicAdd(&g_hpool[batch[n] * CC + c], g_h2[idx]);
}

// ---------------- final 64->1 + sigmoid ----------------
__global__ void k_mlp3(float* __restrict__ out, const float* __restrict__ lw3,
                       const float* __restrict__ lb3) {
    __shared__ float w[64];
    int t = threadIdx.x;
    if (t < 64) w[t] = lw3[t];
    __syncthreads();
    int n = blockIdx.x * blockDim.x + t;
    if (n >= NN) return;
    float s = lb3[0];
    const float* r = &g_mlp2[(size_t)n * 64];
#pragma unroll
    for (int k = 0; k < 64; k++) s += r[k] * w[k];
    out[n] = 1.0f / (1.0f + __expf(-s));
}

// ---------------- host launch ----------------
static float* symaddr(const void* sym) {
    void* p = nullptr;
    cudaGetSymbolAddress(&p, sym);
    return (float*)p;
}

extern "C" void kernel_launch(void* const* d_in, const int* in_sizes, int n_in,
                              void* d_out, int out_size) {
    const float* x     = (const float*)d_in[0];
    const int*   ei    = (const int*)d_in[1];
    const float* ea    = (const float*)d_in[2];
    const int*   batch = (const int*)d_in[3];
    const float *W[3], *as_[3], *ad_[3], *We[3], *ae[3], *b[3];
    for (int l = 0; l < 3; l++) {
        W[l]   = (const float*)d_in[4 + 6 * l];
        as_[l] = (const float*)d_in[5 + 6 * l];
        ad_[l] = (const float*)d_in[6 + 6 * l];
        We[l]  = (const float*)d_in[7 + 6 * l];
        ae[l]  = (const float*)d_in[8 + 6 * l];
        b[l]   = (const float*)d_in[9 + 6 * l];
    }
    const float* lw1 = (const float*)d_in[22];
    const float* lb1 = (const float*)d_in[23];
    const float* lw2 = (const float*)d_in[24];
    const float* lb2 = (const float*)d_in[25];
    const float* lw3 = (const float*)d_in[26];
    const float* lb3 = (const float*)d_in[27];
    float* out = (float*)d_out;

    float* p_xl   = symaddr(g_xl);
    float* p_h[3] = {symaddr(g_h0), symaddr(g_h1), symaddr(g_h2)};
    float* p_m1   = symaddr(g_mlp1);
    float* p_m2   = symaddr(g_mlp2);

    // graph preprocessing (CSR by dst + self-loop edge_attr)
    k_init<<<(NMOL * CC + 255) / 256, 256>>>();
    k_count<<<(EE + 255) / 256, 256>>>(ei);
    k_scan<<<1, 1024>>>();
    k_scatter<<<(EP + 255) / 256, 256>>>(ei);
    k_ealoop<<<(NN * EDD + 255) / 256, 256>>>(ea);
    k_wea3<<<1, 384>>>(We[0], ae[0], We[1], ae[1], We[2], ae[2]);

    const float* lin[3] = {x, p_h[0], p_h[1]};
    const int kdim[3]   = {IND, CC, CC};
    const int gx = (NN + 127) / 128;

    for (int l = 0; l < 3; l++) {
        k_gemm_tc<0><<<dim3(gx, CC / 64), 256>>>(lin[l], W[l], p_xl, nullptr,
                                                 NN, kdim[l], CC, 0, nullptr);
        k_attn<<<(NN * HH + 255) / 256, 256>>>(as_[l], ad_[l]);
        k_alpha<<<(EP + 255) / 256, 256>>>(ea, l, ei);
        k_agg<<<NN, 256>>>(p_h[l], b[l]);
    }

    k_pool<<<(NN * CC + 255) / 256, 256>>>(batch);
    // MLP1 with fused concat gather: K = 1024, N = 96
    k_gemm_tc<1><<<dim3(gx, 2), 256>>>(nullptr, lw1, p_m1, lb1, NN, 1024, 96, 1, batch);
    k_gemm_tc<0><<<dim3(gx, 1), 256>>>(p_m1, lw2, p_m2, lb2, NN, 96, 64, 1, nullptr);
    k_mlp3<<<(NN + 255) / 256, 256>>>(out, lw3, lb3);
}

// round 4
// speedup vs baseline: 1.2690x; 1.1536x over previous
#include <cuda_runtime.h>
#include <math.h>
#include <stdint.h>

#define NN   50000
#define EE   800000
#define EP   850000   // EE + NN self loops
#define IND  64
#define EDD  16
#define HH   8
#define DD   32
#define CC   256      // H*D
#define NMOL 500
#define CH   128      // edge chunk per block in fused gatconv

// ---------------- scratch (static device globals; no allocation) ----------------
__device__ float g_ea_loop[NN * EDD];
__device__ int   g_counts[NN];
__device__ int   g_rowstart[NN + 1];
__device__ int   g_cursor[NN];
__device__ int   g_perm[EP];
__device__ int   g_srcs[EP];
__device__ float g_asrc[NN * HH];
__device__ float g_adst[NN * HH];
__device__ float g_xl[(size_t)NN * CC];
__device__ float g_h0[(size_t)NN * CC];
__device__ float g_h1[(size_t)NN * CC];
__device__ float g_h2[(size_t)NN * CC];
__device__ float g_wea[3 * EDD * HH];
__device__ float g_hpool[NMOL * CC];
__device__ int   g_molstart[NMOL + 1];
__device__ float g_mlp1[(size_t)NN * 96];
__device__ float g_mlp2[(size_t)NN * 64];

// ---------------- init: counts=1 (self loop) ----------------
__global__ void k_init() {
    int i = blockIdx.x * blockDim.x + threadIdx.x;
    if (i < NN) g_counts[i] = 1;
}

// ---------------- in-degree count: one atomic per edge ----------------
__global__ void k_count(const int* __restrict__ ei) {
    int e = blockIdx.x * blockDim.x + threadIdx.x;
    if (e < EE) atomicAdd(&g_counts[ei[EE + e]], 1);
}

// ---------------- single-block exclusive scan over counts -> rowstart, cursor ----------------
__global__ void k_scan() {
    __shared__ int part[1024];
    int t = threadIdx.x;
    const int chunk = (NN + 1023) / 1024;
    int start = t * chunk;
    int end = start + chunk; if (end > NN) end = NN;
    int s = 0;
    for (int i = start; i < end; i++) s += g_counts[i];
    part[t] = s;
    __syncthreads();
    for (int off = 1; off < 1024; off <<= 1) {
        int u = (t >= off) ? part[t - off] : 0;
        __syncthreads();
        part[t] += u;
        __syncthreads();
    }
    int run = part[t] - s;  // exclusive prefix
    for (int i = start; i < end; i++) {
        g_rowstart[i] = run;
        g_cursor[i]   = run;
        run += g_counts[i];
    }
    if (t == 1023) g_rowstart[NN] = part[1023];
}

// ---------------- scatter edges (incl. self loops) into CSR order ----------------
__global__ void k_scatter(const int* __restrict__ ei) {
    int idx = blockIdx.x * blockDim.x + threadIdx.x;
    if (idx >= EP) return;
    int s, d;
    if (idx < EE) { s = ei[idx]; d = ei[EE + idx]; }
    else          { s = idx - EE; d = s; }
    int pos = atomicAdd(&g_cursor[d], 1);
    g_perm[pos] = idx;
    g_srcs[pos] = s;
}

// ---------------- self-loop edge_attr (fill='add'): sum over CSR row's real edges ----------------
__global__ void k_ealoop(const float* __restrict__ ea) {
    int idx = blockIdx.x * blockDim.x + threadIdx.x;
    if (idx >= NN * EDD) return;
    int n = idx >> 4, i = idx & 15;
    int rs = g_rowstart[n], re = g_rowstart[n + 1];
    float s = 0.f;
    for (int p = rs; p < re; p++) {
        int e = g_perm[p];
        if (e < EE) s += ea[(size_t)e * EDD + i];
    }
    g_ea_loop[idx] = s;
}

// ---------------- Wea[l][i][h] = sum_d We_l[i, h*D+d] * ae_l[h,d], all 3 layers ----------------
__global__ void k_wea3(const float* __restrict__ We0, const float* __restrict__ ae0,
                       const float* __restrict__ We1, const float* __restrict__ ae1,
                       const float* __restrict__ We2, const float* __restrict__ ae2) {
    int t = threadIdx.x;  // 384
    int l = t >> 7, r = t & 127;
    int i = r >> 3, h = r & 7;
    const float* We = (l == 0) ? We0 : (l == 1) ? We1 : We2;
    const float* ae = (l == 0) ? ae0 : (l == 1) ? ae1 : ae2;
    float s = 0.f;
    for (int dd = 0; dd < DD; dd++) s += We[i * CC + h * DD + dd] * ae[h * DD + dd];
    g_wea[l * EDD * HH + i * HH + h] = s;
}

// ---------------- molecule row boundaries (batch is sorted) ----------------
__global__ void k_molstart(const int* __restrict__ batch) {
    int n = blockIdx.x * blockDim.x + threadIdx.x;
    if (n >= NN) return;
    int b = batch[n];
    int prev = (n == 0) ? -1 : batch[n - 1];
    for (int m = prev + 1; m <= b; m++) g_molstart[m] = n;
    if (n == NN - 1)
        for (int m = b + 1; m <= NMOL; m++) g_molstart[m] = NN;
}

// ---------------- TF32 helpers ----------------
__device__ __forceinline__ uint32_t f2tf32(float x) {
    uint32_t r;
    asm("cvt.rna.tf32.f32 %0, %1;" : "=r"(r) : "f"(x));
    return r;
}
__device__ __forceinline__ void split_tf32(float x, uint32_t& hi, uint32_t& lo) {
    hi = f2tf32(x);
    lo = f2tf32(x - __uint_as_float(hi));
}
__device__ __forceinline__ void mma_tf32(float* d, const uint32_t* a, const uint32_t* b) {
    asm volatile(
        "mma.sync.aligned.m16n8k8.row.col.f32.tf32.tf32.f32 "
        "{%0,%1,%2,%3}, {%4,%5,%6,%7}, {%8,%9}, {%0,%1,%2,%3};\n"
        : "+f"(d[0]), "+f"(d[1]), "+f"(d[2]), "+f"(d[3])
        : "r"(a[0]), "r"(a[1]), "r"(a[2]), "r"(a[3]), "r"(b[0]), "r"(b[1]));
}

// ---------------- tensor-core GEMM (tf32x3): C[M,N] = A[M,K] @ B[K,N] (+bias, leaky) ----------------
// BM=128, BN=64, BK=16. 256 threads = 8 warps (4 along M x 2 along N), warp tile 32x32.
// MODE 0: A plain row-major. MODE 1: virtual concat row [h0|h1|h2|hpool[batch]], K=1024.
template<int MODE>
__global__ void k_gemm_tc(const float* __restrict__ A, const float* __restrict__ B,
                          float* __restrict__ C, const float* __restrict__ bias,
                          int M, int K, int N, int act, const int* __restrict__ batch) {
    __shared__ uint32_t As_hi[128][20];
    __shared__ uint32_t As_lo[128][20];
    __shared__ uint32_t Bs_hi[16][72];
    __shared__ uint32_t Bs_lo[16][72];

    const int t    = threadIdx.x;
    const int m0   = blockIdx.x * 128;
    const int n0   = blockIdx.y * 64;
    const int warp = t >> 5, lane = t & 31;
    const int wm = (warp & 3) * 32;
    const int wn = (warp >> 2) * 32;
    const int g  = lane >> 2, tg = lane & 3;

    const int ar  = t >> 2;
    const int ac4 = (t & 3) * 4;
    const int br  = t >> 4;
    const int bc4 = (t & 15) * 4;

    int bidx0 = 0, bidx1 = 0;
    if (MODE == 1) {
        if (m0 + ar < M)      bidx0 = batch[m0 + ar];
        if (m0 + ar + 64 < M) bidx1 = batch[m0 + ar + 64];
    }

    float acc[2][4][4];
#pragma unroll
    for (int i = 0; i < 2; i++)
#pragma unroll
        for (int j = 0; j < 4; j++)
#pragma unroll
            for (int c = 0; c < 4; c++) acc[i][j][c] = 0.f;

    for (int k0 = 0; k0 < K; k0 += 16) {
#pragma unroll
        for (int r = 0; r < 2; r++) {
            int row = ar + r * 64;
            int gm  = m0 + row;
            float4 v = make_float4(0.f, 0.f, 0.f, 0.f);
            if (gm < M) {
                int gk = k0 + ac4;
                if (MODE == 0) {
                    v = *reinterpret_cast<const float4*>(A + (size_t)gm * K + gk);
                } else {
                    int bidx = r ? bidx1 : bidx0;
                    const float* src;
                    if      (gk < 256) src = g_h0 + (size_t)gm * CC + gk;
                    else if (gk < 512) src = g_h1 + (size_t)gm * CC + (gk - 256);
                    else if (gk < 768) src = g_h2 + (size_t)gm * CC + (gk - 512);
                    else               src = g_hpool + (size_t)bidx * CC + (gk - 768);
                    v = *reinterpret_cast<const float4*>(src);
                }
            }
            float vv[4] = {v.x, v.y, v.z, v.w};
#pragma unroll
            for (int c = 0; c < 4; c++) {
                uint32_t hi, lo;
                split_tf32(vv[c], hi, lo);
                As_hi[row][ac4 + c] = hi;
                As_lo[row][ac4 + c] = lo;
            }
        }
        {
            int gk = k0 + br;
            int gn = n0 + bc4;
            float vv[4] = {0.f, 0.f, 0.f, 0.f};
            const float* bp = B + (size_t)gk * N + gn;
            if (gn + 3 < N) {
                float4 v = *reinterpret_cast<const float4*>(bp);
                vv[0] = v.x; vv[1] = v.y; vv[2] = v.z; vv[3] = v.w;
            } else {
#pragma unroll
                for (int c = 0; c < 4; c++) if (gn + c < N) vv[c] = bp[c];
            }
#pragma unroll
            for (int c = 0; c < 4; c++) {
                uint32_t hi, lo;
                split_tf32(vv[c], hi, lo);
                Bs_hi[br][bc4 + c] = hi;
                Bs_lo[br][bc4 + c] = lo;
            }
        }
        __syncthreads();

#pragma unroll
        for (int ks = 0; ks < 2; ks++) {
            const int kk = ks * 8;
            uint32_t ah[2][4], al[2][4];
#pragma unroll
            for (int i2 = 0; i2 < 2; i2++) {
                int rb = wm + i2 * 16;
                ah[i2][0] = As_hi[rb + g     ][kk + tg];
                ah[i2][1] = As_hi[rb + g + 8 ][kk + tg];
                ah[i2][2] = As_hi[rb + g     ][kk + tg + 4];
                ah[i2][3] = As_hi[rb + g + 8 ][kk + tg + 4];
                al[i2][0] = As_lo[rb + g     ][kk + tg];
                al[i2][1] = As_lo[rb + g + 8 ][kk + tg];
                al[i2][2] = As_lo[rb + g     ][kk + tg + 4];
                al[i2][3] = As_lo[rb + g + 8 ][kk + tg + 4];
            }
            uint32_t bh[4][2], bl[4][2];
#pragma unroll
            for (int j = 0; j < 4; j++) {
                int cb = wn + j * 8 + g;
                bh[j][0] = Bs_hi[kk + tg    ][cb];
                bh[j][1] = Bs_hi[kk + tg + 4][cb];
                bl[j][0] = Bs_lo[kk + tg    ][cb];
                bl[j][1] = Bs_lo[kk + tg + 4][cb];
            }
#pragma unroll
            for (int i2 = 0; i2 < 2; i2++)
#pragma unroll
                for (int j = 0; j < 4; j++) {
                    mma_tf32(acc[i2][j], ah[i2], bl[j]);
                    mma_tf32(acc[i2][j], al[i2], bh[j]);
                    mma_tf32(acc[i2][j], ah[i2], bh[j]);
                }
        }
        __syncthreads();
    }

#pragma unroll
    for (int i2 = 0; i2 < 2; i2++) {
#pragma unroll
        for (int j = 0; j < 4; j++) {
            int col = n0 + wn + j * 8 + tg * 2;
#pragma unroll
            for (int rr = 0; rr < 2; rr++) {
                int row = m0 + wm + i2 * 16 + g + rr * 8;
                if (row >= M || col >= N) continue;
                float v0 = acc[i2][j][rr * 2 + 0];
                float v1 = acc[i2][j][rr * 2 + 1];
                if (bias) { v0 += bias[col]; v1 += bias[col + 1]; }
                if (act == 1) {
                    v0 = (v0 > 0.f) ? v0 : 0.01f * v0;
                    v1 = (v1 > 0.f) ? v1 : 0.01f * v1;
                }
                *reinterpret_cast<float2*>(C + (size_t)row * N + col) = make_float2(v0, v1);
            }
        }
    }
}

// ---------------- per-(node,head) attention scalars from xl ----------------
__global__ void k_attn(const float* __restrict__ as_, const float* __restrict__ ad_) {
    int idx = blockIdx.x * blockDim.x + threadIdx.x;
    if (idx >= NN * HH) return;
    int n = idx >> 3, h = idx & 7;
    const float* xr = &g_xl[(size_t)n * CC + h * DD];
    float ss = 0.f, sd = 0.f;
#pragma unroll
    for (int dd = 0; dd < DD; dd++) {
        float v = xr[dd];
        ss += v * as_[h * DD + dd];
        sd += v * ad_[h * DD + dd];
    }
    g_asrc[idx] = ss;
    g_adst[idx] = sd;
}

// ---------------- FUSED gatconv: per-node block computes logits, softmax, aggregate ----------------
// 256 threads/block, block = dst node. Online softmax over chunks of CH edges.
__global__ void k_gatconv(const float* __restrict__ edge_attr, int layer,
                          float* __restrict__ out, const float* __restrict__ bias) {
    const int n = blockIdx.x;
    const int rs = g_rowstart[n], re = g_rowstart[n + 1];
    const int t = threadIdx.x;
    const int h = t >> 5;

    __shared__ float swea[EDD * HH];
    __shared__ float s_adst[HH];
    __shared__ int   s_s[CH];
    __shared__ float s_lg[CH * HH];
    __shared__ float s_m[HH], s_sum[HH], s_scale[HH], s_red[HH];

    if (t < EDD * HH) swea[t] = g_wea[layer * EDD * HH + t];
    if (t < HH) {
        s_adst[t] = g_adst[n * HH + t];
        s_m[t]   = -1e30f;
        s_sum[t] = 0.f;
    }
    __syncthreads();

    float acc = 0.f;

    for (int c0 = rs; c0 < re; c0 += CH) {
        const int cnt = min(CH, re - c0);

        // ---- phase 1: logits for this chunk (edge-parallel) ----
        for (int i = t; i < cnt; i += 256) {
            int p = c0 + i;
            int e = g_perm[p];
            int s = g_srcs[p];
            s_s[i] = s;
            const float* ear = (e < EE) ? (edge_attr + (size_t)e * EDD)
                                        : (g_ea_loop + (size_t)(e - EE) * EDD);
            float lg[HH];
#pragma unroll
            for (int h2 = 0; h2 < HH; h2++) lg[h2] = g_asrc[s * HH + h2] + s_adst[h2];
#pragma unroll
            for (int j = 0; j < EDD; j++) {
                float ev = ear[j];
#pragma unroll
                for (int h2 = 0; h2 < HH; h2++) lg[h2] += ev * swea[j * HH + h2];
            }
#pragma unroll
            for (int h2 = 0; h2 < HH; h2++) {
                float v = lg[h2];
                s_lg[i * HH + h2] = (v > 0.f) ? v : 0.2f * v;
            }
        }
        __syncthreads();

        // ---- chunk max per head ----
        if (t < 64) {
            int h2 = t >> 3, j = t & 7;
            float m = -1e30f;
            for (int i = j; i < cnt; i += 8) m = fmaxf(m, s_lg[i * HH + h2]);
#pragma unroll
            for (int o = 1; o < 8; o <<= 1) m = fmaxf(m, __shfl_xor_sync(0xffffffffu, m, o, 8));
            if (j == 0) s_red[h2] = m;
        }
        __syncthreads();

        // ---- update running max / scale ----
        if (t < HH) {
            float mo = s_m[t];
            float mn = fmaxf(mo, s_red[t]);
            s_scale[t] = __expf(mo - mn);
            s_m[t] = mn;
            s_sum[t] *= s_scale[t];
        }
        __syncthreads();

        acc *= s_scale[h];

        // ---- weights + chunk sum ----
        if (t < 64) {
            int h2 = t >> 3, j = t & 7;
            float m = s_m[h2];
            float ss = 0.f;
            for (int i = j; i < cnt; i += 8) {
                float w = __expf(s_lg[i * HH + h2] - m);
                s_lg[i * HH + h2] = w;
                ss += w;
            }
#pragma unroll
            for (int o = 1; o < 8; o <<= 1) ss += __shfl_xor_sync(0xffffffffu, ss, o, 8);
            if (j == 0) s_red[h2] = ss;
        }
        __syncthreads();
        if (t < HH) s_sum[t] += s_red[t];

        // ---- phase 2: weighted aggregate (channel-parallel, independent loads) ----
#pragma unroll 4
        for (int i = 0; i < cnt; i++) {
            acc += s_lg[i * HH + h] * g_xl[(size_t)s_s[i] * CC + t];
        }
        __syncthreads();
    }

    out[(size_t)n * CC + t] = acc / s_sum[h] + bias[t];
}

// ---------------- atomic-free pooling: block per molecule (batch sorted) ----------------
__global__ void k_pool_seg() {
    int m = blockIdx.x;
    int t = threadIdx.x;
    int rs = g_molstart[m], re = g_molstart[m + 1];
    float s = 0.f;
    for (int n = rs; n < re; n++) s += g_h2[(size_t)n * CC + t];
    g_hpool[(size_t)m * CC + t] = s;
}

// ---------------- final 64->1 + sigmoid ----------------
__global__ void k_mlp3(float* __restrict__ out, const float* __restrict__ lw3,
                       const float* __restrict__ lb3) {
    __shared__ float w[64];
    int t = threadIdx.x;
    if (t < 64) w[t] = lw3[t];
    __syncthreads();
    int n = blockIdx.x * blockDim.x + t;
    if (n >= NN) return;
    float s = lb3[0];
    const float* r = &g_mlp2[(size_t)n * 64];
#pragma unroll
    for (int k = 0; k < 64; k++) s += r[k] * w[k];
    out[n] = 1.0f / (1.0f + __expf(-s));
}

// ---------------- host launch ----------------
static float* symaddr(const void* sym) {
    void* p = nullptr;
    cudaGetSymbolAddress(&p, sym);
    return (float*)p;
}

extern "C" void kernel_launch(void* const* d_in, const int* in_sizes, int n_in,
                              void* d_out, int out_size) {
    const float* x     = (const float*)d_in[0];
    const int*   ei    = (const int*)d_in[1];
    const float* ea    = (const float*)d_in[2];
    const int*   batch = (const int*)d_in[3];
    const float *W[3], *as_[3], *ad_[3], *We[3], *ae[3], *b[3];
    for (int l = 0; l < 3; l++) {
        W[l]   = (const float*)d_in[4 + 6 * l];
        as_[l] = (const float*)d_in[5 + 6 * l];
        ad_[l] = (const float*)d_in[6 + 6 * l];
        We[l]  = (const float*)d_in[7 + 6 * l];
        ae[l]  = (const float*)d_in[8 + 6 * l];
        b[l]   = (const float*)d_in[9 + 6 * l];
    }
    const float* lw1 = (const float*)d_in[22];
    const float* lb1 = (const float*)d_in[23];
    const float* lw2 = (const float*)d_in[24];
    const float* lb2 = (const float*)d_in[25];
    const float* lw3 = (const float*)d_in[26];
    const float* lb3 = (const float*)d_in[27];
    float* out = (float*)d_out;

    float* p_xl   = symaddr(g_xl);
    float* p_h[3] = {symaddr(g_h0), symaddr(g_h1), symaddr(g_h2)};
    float* p_m1   = symaddr(g_mlp1);
    float* p_m2   = symaddr(g_mlp2);

    // graph preprocessing (CSR by dst + self-loop edge_attr + molecule ranges)
    k_init<<<(NN + 255) / 256, 256>>>();
    k_count<<<(EE + 255) / 256, 256>>>(ei);
    k_scan<<<1, 1024>>>();
    k_scatter<<<(EP + 255) / 256, 256>>>(ei);
    k_ealoop<<<(NN * EDD + 255) / 256, 256>>>(ea);
    k_wea3<<<1, 384>>>(We[0], ae[0], We[1], ae[1], We[2], ae[2]);
    k_molstart<<<(NN + 255) / 256, 256>>>(batch);

    const float* lin[3] = {x, p_h[0], p_h[1]};
    const int kdim[3]   = {IND, CC, CC};
    const int gx = (NN + 127) / 128;

    for (int l = 0; l < 3; l++) {
        k_gemm_tc<0><<<dim3(gx, CC / 64), 256>>>(lin[l], W[l], p_xl, nullptr,
                                                 NN, kdim[l], CC, 0, nullptr);
        k_attn<<<(NN * HH + 255) / 256, 256>>>(as_[l], ad_[l]);
        k_gatconv<<<NN, 256>>>(ea, l, p_h[l], b[l]);
    }

    k_pool_seg<<<NMOL, 256>>>();
    // MLP1 with fused concat gather: K = 1024, N = 96
    k_gemm_tc<1><<<dim3(gx, 2), 256>>>(nullptr, lw1, p_m1, lb1, NN, 1024, 96, 1, batch);
    k_gemm_tc<0><<<dim3(gx, 1), 256>>>(p_m1, lw2, p_m2, lb2, NN, 96, 64, 1, nullptr);
    k_mlp3<<<(NN + 255) / 256, 256>>>(out, lw3, lb3);
}

// round 5
// speedup vs baseline: 1.4873x; 1.1720x over previous
#include <cuda_runtime.h>
#include <cuda_bf16.h>
#include <math.h>
#include <stdint.h>

#define NN   50000
#define EE   800000
#define EP   850000   // EE + NN self loops
#define IND  64
#define EDD  16
#define HH   8
#define DD   32
#define CC   256      // H*D
#define NMOL 500
#define CH   128      // edge chunk per block in fused gatconv

// ---------------- scratch (static device globals; no allocation) ----------------
__device__ float g_ea_loop[NN * EDD];
__device__ int   g_counts[NN];
__device__ int   g_rowstart[NN + 1];
__device__ int   g_cursor[NN];
__device__ int   g_perm[EP];
__device__ int   g_srcs[EP];
__device__ float g_asrc[NN * HH];
__device__ float g_adst[NN * HH];
__device__ float g_xl[(size_t)NN * CC];
__device__ float g_h0[(size_t)NN * CC];
__device__ float g_h1[(size_t)NN * CC];
__device__ float g_h2[(size_t)NN * CC];
__device__ float g_wea[3 * EDD * HH];
__device__ float g_hpool[NMOL * CC];
__device__ int   g_molstart[NMOL + 1];
__device__ float g_mlp1[(size_t)NN * 96];
__device__ float g_mlp2[(size_t)NN * 64];

// ---------------- init: counts=1 (self loop) ----------------
__global__ void k_init() {
    int i = blockIdx.x * blockDim.x + threadIdx.x;
    if (i < NN) g_counts[i] = 1;
}

// ---------------- in-degree count: one atomic per edge ----------------
__global__ void k_count(const int* __restrict__ ei) {
    int e = blockIdx.x * blockDim.x + threadIdx.x;
    if (e < EE) atomicAdd(&g_counts[ei[EE + e]], 1);
}

// ---------------- single-block exclusive scan over counts -> rowstart, cursor ----------------
__global__ void k_scan() {
    __shared__ int part[1024];
    int t = threadIdx.x;
    const int chunk = (NN + 1023) / 1024;
    int start = t * chunk;
    int end = start + chunk; if (end > NN) end = NN;
    int s = 0;
    for (int i = start; i < end; i++) s += g_counts[i];
    part[t] = s;
    __syncthreads();
    for (int off = 1; off < 1024; off <<= 1) {
        int u = (t >= off) ? part[t - off] : 0;
        __syncthreads();
        part[t] += u;
        __syncthreads();
    }
    int run = part[t] - s;  // exclusive prefix
    for (int i = start; i < end; i++) {
        g_rowstart[i] = run;
        g_cursor[i]   = run;
        run += g_counts[i];
    }
    if (t == 1023) g_rowstart[NN] = part[1023];
}

// ---------------- scatter edges (incl. self loops) into CSR order ----------------
__global__ void k_scatter(const int* __restrict__ ei) {
    int idx = blockIdx.x * blockDim.x + threadIdx.x;
    if (idx >= EP) return;
    int s, d;
    if (idx < EE) { s = ei[idx]; d = ei[EE + idx]; }
    else          { s = idx - EE; d = s; }
    int pos = atomicAdd(&g_cursor[d], 1);
    g_perm[pos] = idx;
    g_srcs[pos] = s;
}

// ---------------- self-loop edge_attr (fill='add'): sum over CSR row's real edges ----------------
__global__ void k_ealoop(const float* __restrict__ ea) {
    int idx = blockIdx.x * blockDim.x + threadIdx.x;
    if (idx >= NN * EDD) return;
    int n = idx >> 4, i = idx & 15;
    int rs = g_rowstart[n], re = g_rowstart[n + 1];
    float s = 0.f;
    for (int p = rs; p < re; p++) {
        int e = g_perm[p];
        if (e < EE) s += ea[(size_t)e * EDD + i];
    }
    g_ea_loop[idx] = s;
}

// ---------------- Wea[l][i][h] = sum_d We_l[i, h*D+d] * ae_l[h,d], all 3 layers ----------------
__global__ void k_wea3(const float* __restrict__ We0, const float* __restrict__ ae0,
                       const float* __restrict__ We1, const float* __restrict__ ae1,
                       const float* __restrict__ We2, const float* __restrict__ ae2) {
    int t = threadIdx.x;  // 384
    int l = t >> 7, r = t & 127;
    int i = r >> 3, h = r & 7;
    const float* We = (l == 0) ? We0 : (l == 1) ? We1 : We2;
    const float* ae = (l == 0) ? ae0 : (l == 1) ? ae1 : ae2;
    float s = 0.f;
    for (int dd = 0; dd < DD; dd++) s += We[i * CC + h * DD + dd] * ae[h * DD + dd];
    g_wea[l * EDD * HH + i * HH + h] = s;
}

// ---------------- molecule row boundaries (batch is sorted) ----------------
__global__ void k_molstart(const int* __restrict__ batch) {
    int n = blockIdx.x * blockDim.x + threadIdx.x;
    if (n >= NN) return;
    int b = batch[n];
    int prev = (n == 0) ? -1 : batch[n - 1];
    for (int m = prev + 1; m <= b; m++) g_molstart[m] = n;
    if (n == NN - 1)
        for (int m = b + 1; m <= NMOL; m++) g_molstart[m] = NN;
}

// ---------------- bf16 split helpers ----------------
__device__ __forceinline__ void split_bf2(float x, float y, uint32_t& hi, uint32_t& lo) {
    __nv_bfloat162 h = __floats2bfloat162_rn(x, y);
    float rx = x - __bfloat162float(h.x);
    float ry = y - __bfloat162float(h.y);
    __nv_bfloat162 l = __floats2bfloat162_rn(rx, ry);
    hi = *reinterpret_cast<uint32_t*>(&h);
    lo = *reinterpret_cast<uint32_t*>(&l);
}
__device__ __forceinline__ void mma_bf16(float* d, const uint32_t* a, const uint32_t* b) {
    asm volatile(
        "mma.sync.aligned.m16n8k16.row.col.f32.bf16.bf16.f32 "
        "{%0,%1,%2,%3}, {%4,%5,%6,%7}, {%8,%9}, {%0,%1,%2,%3};\n"
        : "+f"(d[0]), "+f"(d[1]), "+f"(d[2]), "+f"(d[3])
        : "r"(a[0]), "r"(a[1]), "r"(a[2]), "r"(a[3]), "r"(b[0]), "r"(b[1]));
}

// ---------------- tensor-core GEMM (bf16x3): C[M,N] = A[M,K] @ B[K,N] (+bias, leaky) ----------------
// BM=128, BN=64, BK=16. 256 threads = 8 warps (4 along M x 2 along N), warp tile 32x32.
// Smem stores bf16 pairs (2 k per u32): As[row][8 u32], Bs[col][8 u32] (k-pairs), stride 12 pad.
// MODE 0: A plain row-major. MODE 1: virtual concat row [h0|h1|h2|hpool[batch]], K=1024.
template<int MODE>
__global__ void k_gemm_tc(const float* __restrict__ A, const float* __restrict__ B,
                          float* __restrict__ C, const float* __restrict__ bias,
                          int M, int K, int N, int act, const int* __restrict__ batch) {
    __shared__ uint32_t As_hi[128][12];
    __shared__ uint32_t As_lo[128][12];
    __shared__ uint32_t Bs_hi[64][12];
    __shared__ uint32_t Bs_lo[64][12];

    const int t    = threadIdx.x;
    const int m0   = blockIdx.x * 128;
    const int n0   = blockIdx.y * 64;
    const int warp = t >> 5, lane = t & 31;
    const int wm = (warp & 3) * 32;
    const int wn = (warp >> 2) * 32;
    const int g  = lane >> 2, tg = lane & 3;

    // A loader: thread handles rows ar, ar+64; k offsets ac4..ac4+3
    const int ar  = t >> 2;
    const int ac4 = (t & 3) * 4;
    // B loader: thread handles col bn, k-pairs bj and bj+4 (k = 2*bj, 2*bj+8)
    const int bn = t & 63;
    const int bj = t >> 6;   // 0..3

    int bidx0 = 0, bidx1 = 0;
    if (MODE == 1) {
        if (m0 + ar < M)      bidx0 = batch[m0 + ar];
        if (m0 + ar + 64 < M) bidx1 = batch[m0 + ar + 64];
    }

    float acc[2][4][4];
#pragma unroll
    for (int i = 0; i < 2; i++)
#pragma unroll
        for (int j = 0; j < 4; j++)
#pragma unroll
            for (int c = 0; c < 4; c++) acc[i][j][c] = 0.f;

    for (int k0 = 0; k0 < K; k0 += 16) {
        // ---- load A tile (128 x 16) as bf16 hi/lo pairs ----
#pragma unroll
        for (int r = 0; r < 2; r++) {
            int row = ar + r * 64;
            int gm  = m0 + row;
            float4 v = make_float4(0.f, 0.f, 0.f, 0.f);
            if (gm < M) {
                int gk = k0 + ac4;
                if (MODE == 0) {
                    v = *reinterpret_cast<const float4*>(A + (size_t)gm * K + gk);
                } else {
                    int bidx = r ? bidx1 : bidx0;
                    const float* src;
                    if      (gk < 256) src = g_h0 + (size_t)gm * CC + gk;
                    else if (gk < 512) src = g_h1 + (size_t)gm * CC + (gk - 256);
                    else if (gk < 768) src = g_h2 + (size_t)gm * CC + (gk - 512);
                    else               src = g_hpool + (size_t)bidx * CC + (gk - 768);
                    v = *reinterpret_cast<const float4*>(src);
                }
            }
            uint32_t h0_, l0_, h1_, l1_;
            split_bf2(v.x, v.y, h0_, l0_);
            split_bf2(v.z, v.w, h1_, l1_);
            int kp = ac4 >> 1;
            As_hi[row][kp    ] = h0_;
            As_hi[row][kp + 1] = h1_;
            As_lo[row][kp    ] = l0_;
            As_lo[row][kp + 1] = l1_;
        }
        // ---- load B tile (16 x 64) transposed into [n][k-pair] bf16 ----
        {
            int gn = n0 + bn;
            bool ok = (gn < N);
#pragma unroll
            for (int q = 0; q < 2; q++) {
                int kp = bj + q * 4;            // u32 index (k pair)
                int gk = k0 + kp * 2;
                float v0 = 0.f, v1 = 0.f;
                if (ok) {
                    v0 = B[(size_t)gk * N + gn];
                    v1 = B[(size_t)(gk + 1) * N + gn];
                }
                uint32_t hi, lo;
                split_bf2(v0, v1, hi, lo);
                Bs_hi[bn][kp] = hi;
                Bs_lo[bn][kp] = lo;
            }
        }
        __syncthreads();

        // ---- fragments + 24 MMAs (k16) ----
        uint32_t ah[2][4], al[2][4];
#pragma unroll
        for (int i2 = 0; i2 < 2; i2++) {
            int rb = wm + i2 * 16;
            ah[i2][0] = As_hi[rb + g     ][tg];
            ah[i2][1] = As_hi[rb + g + 8 ][tg];
            ah[i2][2] = As_hi[rb + g     ][tg + 4];
            ah[i2][3] = As_hi[rb + g + 8 ][tg + 4];
            al[i2][0] = As_lo[rb + g     ][tg];
            al[i2][1] = As_lo[rb + g + 8 ][tg];
            al[i2][2] = As_lo[rb + g     ][tg + 4];
            al[i2][3] = As_lo[rb + g + 8 ][tg + 4];
        }
        uint32_t bh[4][2], bl[4][2];
#pragma unroll
        for (int j = 0; j < 4; j++) {
            int cb = wn + j * 8 + g;
            bh[j][0] = Bs_hi[cb][tg];
            bh[j][1] = Bs_hi[cb][tg + 4];
            bl[j][0] = Bs_lo[cb][tg];
            bl[j][1] = Bs_lo[cb][tg + 4];
        }
#pragma unroll
        for (int i2 = 0; i2 < 2; i2++)
#pragma unroll
            for (int j = 0; j < 4; j++) {
                mma_bf16(acc[i2][j], ah[i2], bl[j]);   // hi * lo
                mma_bf16(acc[i2][j], al[i2], bh[j]);   // lo * hi
                mma_bf16(acc[i2][j], ah[i2], bh[j]);   // hi * hi
            }
        __syncthreads();
    }

    // ---- epilogue ----
#pragma unroll
    for (int i2 = 0; i2 < 2; i2++) {
#pragma unroll
        for (int j = 0; j < 4; j++) {
            int col = n0 + wn + j * 8 + tg * 2;
#pragma unroll
            for (int rr = 0; rr < 2; rr++) {
                int row = m0 + wm + i2 * 16 + g + rr * 8;
                if (row >= M || col >= N) continue;
                float v0 = acc[i2][j][rr * 2 + 0];
                float v1 = acc[i2][j][rr * 2 + 1];
                if (bias) { v0 += bias[col]; v1 += bias[col + 1]; }
                if (act == 1) {
                    v0 = (v0 > 0.f) ? v0 : 0.01f * v0;
                    v1 = (v1 > 0.f) ? v1 : 0.01f * v1;
                }
                *reinterpret_cast<float2*>(C + (size_t)row * N + col) = make_float2(v0, v1);
            }
        }
    }
}

// ---------------- per-(node,head) attention scalars from xl ----------------
__global__ void k_attn(const float* __restrict__ as_, const float* __restrict__ ad_) {
    int idx = blockIdx.x * blockDim.x + threadIdx.x;
    if (idx >= NN * HH) return;
    int n = idx >> 3, h = idx & 7;
    const float* xr = &g_xl[(size_t)n * CC + h * DD];
    float ss = 0.f, sd = 0.f;
#pragma unroll
    for (int dd = 0; dd < DD; dd++) {
        float v = xr[dd];
        ss += v * as_[h * DD + dd];
        sd += v * ad_[h * DD + dd];
    }
    g_asrc[idx] = ss;
    g_adst[idx] = sd;
}

// ---------------- FUSED gatconv: per-node block computes logits, softmax, aggregate ----------------
__global__ void k_gatconv(const float* __restrict__ edge_attr, int layer,
                          float* __restrict__ out, const float* __restrict__ bias) {
    const int n = blockIdx.x;
    const int rs = g_rowstart[n], re = g_rowstart[n + 1];
    const int t = threadIdx.x;
    const int h = t >> 5;

    __shared__ float swea[EDD * HH];
    __shared__ float s_adst[HH];
    __shared__ int   s_s[CH];
    __shared__ float s_lg[CH * HH];
    __shared__ float s_m[HH], s_sum[HH], s_scale[HH], s_red[HH];

    if (t < EDD * HH) swea[t] = g_wea[layer * EDD * HH + t];
    if (t < HH) {
        s_adst[t] = g_adst[n * HH + t];
        s_m[t]   = -1e30f;
        s_sum[t] = 0.f;
    }
    __syncthreads();

    float acc = 0.f;

    for (int c0 = rs; c0 < re; c0 += CH) {
        const int cnt = min(CH, re - c0);

        for (int i = t; i < cnt; i += 256) {
            int p = c0 + i;
            int e = g_perm[p];
            int s = g_srcs[p];
            s_s[i] = s;
            const float* ear = (e < EE) ? (edge_attr + (size_t)e * EDD)
                                        : (g_ea_loop + (size_t)(e - EE) * EDD);
            float lg[HH];
#pragma unroll
            for (int h2 = 0; h2 < HH; h2++) lg[h2] = g_asrc[s * HH + h2] + s_adst[h2];
#pragma unroll
            for (int j = 0; j < EDD; j++) {
                float ev = ear[j];
#pragma unroll
                for (int h2 = 0; h2 < HH; h2++) lg[h2] += ev * swea[j * HH + h2];
            }
#pragma unroll
            for (int h2 = 0; h2 < HH; h2++) {
                float v = lg[h2];
                s_lg[i * HH + h2] = (v > 0.f) ? v : 0.2f * v;
            }
        }
        __syncthreads();

        if (t < 64) {
            int h2 = t >> 3, j = t & 7;
            float m = -1e30f;
            for (int i = j; i < cnt; i += 8) m = fmaxf(m, s_lg[i * HH + h2]);
#pragma unroll
            for (int o = 1; o < 8; o <<= 1) m = fmaxf(m, __shfl_xor_sync(0xffffffffu, m, o, 8));
            if (j == 0) s_red[h2] = m;
        }
        __syncthreads();

        if (t < HH) {
            float mo = s_m[t];
            float mn = fmaxf(mo, s_red[t]);
            s_scale[t] = __expf(mo - mn);
            s_m[t] = mn;
            s_sum[t] *= s_scale[t];
        }
        __syncthreads();

        acc *= s_scale[h];

        if (t < 64) {
            int h2 = t >> 3, j = t & 7;
            float m = s_m[h2];
            float ss = 0.f;
            for (int i = j; i < cnt; i += 8) {
                float w = __expf(s_lg[i * HH + h2] - m);
                s_lg[i * HH + h2] = w;
                ss += w;
            }
#pragma unroll
            for (int o = 1; o < 8; o <<= 1) ss += __shfl_xor_sync(0xffffffffu, ss, o, 8);
            if (j == 0) s_red[h2] = ss;
        }
        __syncthreads();
        if (t < HH) s_sum[t] += s_red[t];

#pragma unroll 4
        for (int i = 0; i < cnt; i++) {
            acc += s_lg[i * HH + h] * g_xl[(size_t)s_s[i] * CC + t];
        }
        __syncthreads();
    }

    out[(size_t)n * CC + t] = acc / s_sum[h] + bias[t];
}

// ---------------- atomic-free pooling: block per molecule (batch sorted) ----------------
__global__ void k_pool_seg() {
    int m = blockIdx.x;
    int t = threadIdx.x;
    int rs = g_molstart[m], re = g_molstart[m + 1];
    float s = 0.f;
    for (int n = rs; n < re; n++) s += g_h2[(size_t)n * CC + t];
    g_hpool[(size_t)m * CC + t] = s;
}

// ---------------- final 64->1 + sigmoid ----------------
__global__ void k_mlp3(float* __restrict__ out, const float* __restrict__ lw3,
                       const float* __restrict__ lb3) {
    __shared__ float w[64];
    int t = threadIdx.x;
    if (t < 64) w[t] = lw3[t];
    __syncthreads();
    int n = blockIdx.x * blockDim.x + t;
    if (n >= NN) return;
    float s = lb3[0];
    const float* r = &g_mlp2[(size_t)n * 64];
#pragma unroll
    for (int k = 0; k < 64; k++) s += r[k] * w[k];
    out[n] = 1.0f / (1.0f + __expf(-s));
}

// ---------------- host launch ----------------
static float* symaddr(const void* sym) {
    void* p = nullptr;
    cudaGetSymbolAddress(&p, sym);
    return (float*)p;
}

extern "C" void kernel_launch(void* const* d_in, const int* in_sizes, int n_in,
                              void* d_out, int out_size) {
    const float* x     = (const float*)d_in[0];
    const int*   ei    = (const int*)d_in[1];
    const float* ea    = (const float*)d_in[2];
    const int*   batch = (const int*)d_in[3];
    const float *W[3], *as_[3], *ad_[3], *We[3], *ae[3], *b[3];
    for (int l = 0; l < 3; l++) {
        W[l]   = (const float*)d_in[4 + 6 * l];
        as_[l] = (const float*)d_in[5 + 6 * l];
        ad_[l] = (const float*)d_in[6 + 6 * l];
        We[l]  = (const float*)d_in[7 + 6 * l];
        ae[l]  = (const float*)d_in[8 + 6 * l];
        b[l]   = (const float*)d_in[9 + 6 * l];
    }
    const float* lw1 = (const float*)d_in[22];
    const float* lb1 = (const float*)d_in[23];
    const float* lw2 = (const float*)d_in[24];
    const float* lb2 = (const float*)d_in[25];
    const float* lw3 = (const float*)d_in[26];
    const float* lb3 = (const float*)d_in[27];
    float* out = (float*)d_out;

    float* p_xl   = symaddr(g_xl);
    float* p_h[3] = {symaddr(g_h0), symaddr(g_h1), symaddr(g_h2)};
    float* p_m1   = symaddr(g_mlp1);
    float* p_m2   = symaddr(g_mlp2);

    const int gx = (NN + 127) / 128;

    // preprocessing; layer-1 GEMM placed at launch index 3 so ncu (-s 5, with 2
    // harness launches preceding) profiles the heavy GEMM next round.
    k_init<<<(NN + 255) / 256, 256>>>();
    k_count<<<(EE + 255) / 256, 256>>>(ei);
    k_scan<<<1, 1024>>>();
    k_gemm_tc<0><<<dim3(gx, CC / 64), 256>>>(x, W[0], p_xl, nullptr,
                                             NN, IND, CC, 0, nullptr);   // layer-1 GEMM
    k_scatter<<<(EP + 255) / 256, 256>>>(ei);
    k_ealoop<<<(NN * EDD + 255) / 256, 256>>>(ea);
    k_wea3<<<1, 384>>>(We[0], ae[0], We[1], ae[1], We[2], ae[2]);
    k_molstart<<<(NN + 255) / 256, 256>>>(batch);

    // layer 1 attention
    k_attn<<<(NN * HH + 255) / 256, 256>>>(as_[0], ad_[0]);
    k_gatconv<<<NN, 256>>>(ea, 0, p_h[0], b[0]);

    // layers 2, 3
    for (int l = 1; l < 3; l++) {
        k_gemm_tc<0><<<dim3(gx, CC / 64), 256>>>(p_h[l - 1], W[l], p_xl, nullptr,
                                                 NN, CC, CC, 0, nullptr);
        k_attn<<<(NN * HH + 255) / 256, 256>>>(as_[l], ad_[l]);
        k_gatconv<<<NN, 256>>>(ea, l, p_h[l], b[l]);
    }

    k_pool_seg<<<NMOL, 256>>>();
    // MLP1 with fused concat gather: K = 1024, N = 96
    k_gemm_tc<1><<<dim3(gx, 2), 256>>>(nullptr, lw1, p_m1, lb1, NN, 1024, 96, 1, batch);
    k_gemm_tc<0><<<dim3(gx, 1), 256>>>(p_m1, lw2, p_m2, lb2, NN, 96, 64, 1, nullptr);
    k_mlp3<<<(NN + 255) / 256, 256>>>(out, lw3, lb3);
}